// round 7
// baseline (speedup 1.0000x reference)
#include <cuda_runtime.h>
#include <math.h>

#define BB   2
#define SS   2048
#define HIDN 2048
#define NH   16
#define NKV  8
#define HD   128
#define QKVN 4096            // (NH + 2*NKV)*HD
#define MR   (BB*SS)         // 4096 rows

// scratch (device globals: no allocations allowed)
__device__ float g_qkv[(size_t)MR * QKVN];       // 64 MB
__device__ float g_attn[(size_t)MR * (NH*HD)];   // 32 MB

// ---------------------------------------------------------------------------
// SGEMM: C[M,N] = A[M,K] @ B[K,N], all row-major, M%128==N%128==K%8==0
// 128x128 tile, 256 threads, 8x8 per thread in 2x2 quadrants.
// Double-buffered smem: one __syncthreads per K-step, global loads for the
// next tile overlap compute on the current tile.
// __launch_bounds__(256,2): cap 128 regs (est. usage ~100, no spill) to
// guarantee 2 CTAs/SM -> 4 warps/SMSP for latency hiding.
// ---------------------------------------------------------------------------
__global__ __launch_bounds__(256, 2) void sgemm128(
    const float* __restrict__ A, const float* __restrict__ Bm,
    float* __restrict__ C, int M, int N, int K)
{
    __shared__ float As[2][8][128];
    __shared__ float Bs[2][8][128];
    int t  = threadIdx.x;
    int tx = t & 15, ty = t >> 4;
    int row0 = blockIdx.y << 7, col0 = blockIdx.x << 7;

    float acc[8][8];
#pragma unroll
    for (int i = 0; i < 8; i++)
#pragma unroll
        for (int j = 0; j < 8; j++) acc[i][j] = 0.f;

    const float* Ap = A + (size_t)(row0 + (t >> 1)) * K + ((t & 1) << 2);
    const float* Bp = Bm + (size_t)(t >> 5) * N + col0 + ((t & 31) << 2);
    int ar = t >> 1, ak = (t & 1) << 2;
    int bk = t >> 5, bc = (t & 31) << 2;

    // preload tile 0
    float4 a4 = *(const float4*)(Ap);
    float4 b4 = *(const float4*)(Bp);
    As[0][ak + 0][ar] = a4.x; As[0][ak + 1][ar] = a4.y;
    As[0][ak + 2][ar] = a4.z; As[0][ak + 3][ar] = a4.w;
    *(float4*)&Bs[0][bk][bc] = b4;
    __syncthreads();

    int buf = 0;
    for (int k0 = 0; k0 < K; k0 += 8) {
        bool has_next = (k0 + 8) < K;
        if (has_next) {
            a4 = *(const float4*)(Ap + k0 + 8);
            b4 = *(const float4*)(Bp + (size_t)(k0 + 8) * N);
        }
#pragma unroll
        for (int kk = 0; kk < 8; kk++) {
            float a[8], b[8];
            *(float4*)&a[0] = *(float4*)&As[buf][kk][ty << 2];
            *(float4*)&a[4] = *(float4*)&As[buf][kk][64 + (ty << 2)];
            *(float4*)&b[0] = *(float4*)&Bs[buf][kk][tx << 2];
            *(float4*)&b[4] = *(float4*)&Bs[buf][kk][64 + (tx << 2)];
#pragma unroll
            for (int i = 0; i < 8; i++)
#pragma unroll
                for (int j = 0; j < 8; j++)
                    acc[i][j] = fmaf(a[i], b[j], acc[i][j]);
        }
        if (has_next) {
            int nb = buf ^ 1;
            As[nb][ak + 0][ar] = a4.x; As[nb][ak + 1][ar] = a4.y;
            As[nb][ak + 2][ar] = a4.z; As[nb][ak + 3][ar] = a4.w;
            *(float4*)&Bs[nb][bk][bc] = b4;
            __syncthreads();
            buf = nb;
        }
    }
#pragma unroll
    for (int i = 0; i < 8; i++) {
        int r = row0 + ((i < 4) ? ((ty << 2) + i) : (64 + (ty << 2) + i - 4));
        float4 v0 = make_float4(acc[i][0], acc[i][1], acc[i][2], acc[i][3]);
        float4 v1 = make_float4(acc[i][4], acc[i][5], acc[i][6], acc[i][7]);
        *(float4*)&C[(size_t)r * N + col0 + (tx << 2)]      = v0;
        *(float4*)&C[(size_t)r * N + col0 + 64 + (tx << 2)] = v1;
    }
}

// ---------------------------------------------------------------------------
// RoPE in-place on g_qkv (q heads 0..15 at col h*128, k heads at 2048+h*128)
// ---------------------------------------------------------------------------
__global__ void rope_kernel(const int* __restrict__ positions)
{
    int idx = blockIdx.x * blockDim.x + threadIdx.x;
    const int total = MR * 24 * 64;
    if (idx >= total) return;
    int i    = idx & 63;
    int head = (idx >> 6) % 24;
    int row  = idx / (24 * 64);
    int s    = row & (SS - 1);

    int col = (head < NH) ? head * HD : NH * HD + (head - NH) * HD;

    float e    = (float)(2 * i) * (1.0f / 128.0f);
    float invf = 1.0f / powf(10000.0f, e);
    float fr   = (float)positions[s] * invf;
    float c, sn;
    sincosf(fr, &sn, &c);

    float* p = g_qkv + (size_t)row * QKVN + col;
    float x1 = p[i], x2 = p[i + 64];
    p[i]      = x1 * c - x2 * sn;
    p[i + 64] = x2 * c + x1 * sn;
}

// ---------------------------------------------------------------------------
// Flash attention, causal, GQA (2 q heads per kv head), fp32.
// grid: (32 qtiles [reversed], 32 b*h), 256 threads.
// K/V tiles double-buffered in smem; next tile's LDGs issue into registers
// before the current tile's compute, STS after PV, same 2 barriers/iter.
// Thread t: rg=t/16 owns score rows 4*rg..4*rg+3; cg=t%16 owns
// score cols {cg+16j} and O cols {4cg..4cg+3, 64+4cg..64+4cg+3}.
// ---------------------------------------------------------------------------
#define KS_LD   132
#define PS_LD   68
#define KBUF    (64 * KS_LD)
#define VBUF    (64 * 128)
#define ATTN_SMEM ((64*128 + 2*KBUF + 2*VBUF + 64*PS_LD) * 4)  // 183296 B

__global__ __launch_bounds__(256) void attn_kernel()
{
    extern __shared__ float sm[];
    float* Qs = sm;                      // [64][128]
    float* Ks = Qs + 64 * 128;           // [2][64][KS_LD]
    float* Vs = Ks + 2 * KBUF;           // [2][64][128]
    float* Ps = Vs + 2 * VBUF;           // [64][PS_LD]

    int t  = threadIdx.x;
    int rg = t >> 4, cg = t & 15;
    int bh = blockIdx.y;
    int b  = bh >> 4, h = bh & 15;
    int kvh = h >> 1;
    int qt = (int)(gridDim.x - 1) - (int)blockIdx.x;   // heavy tiles first
    int row_base = b * SS + qt * 64;

    // per-thread fixed (r, c4) for KV loads: 8 chunks of 256 threads
    int lr = t >> 5, lc4 = t & 31;       // + it*8 rows per chunk

    // load Q tile [64][128] and KV tile j=0 into buffer 0
    {
        int kv_base = b * SS;            // j = 0
        for (int it = 0; it < 8; it++) {
            int r = lr + (it << 3);
            *(float4*)&Qs[r * 128 + (lc4 << 2)] =
                *(const float4*)&g_qkv[(size_t)(row_base + r) * QKVN + h * HD + (lc4 << 2)];
            const float* kr = &g_qkv[(size_t)(kv_base + r) * QKVN + NH * HD + kvh * HD + (lc4 << 2)];
            *(float4*)&Ks[r * KS_LD + (lc4 << 2)] = *(const float4*)kr;
            *(float4*)&Vs[r * 128   + (lc4 << 2)] = *(const float4*)(kr + NKV * HD);
        }
    }
    __syncthreads();

    float m_i[4], l_i[4], O[4][8];
#pragma unroll
    for (int i = 0; i < 4; i++) {
        m_i[i] = -1e30f; l_i[i] = 0.f;
#pragma unroll
        for (int j = 0; j < 8; j++) O[i][j] = 0.f;
    }

    const float scale = 0.08838834764831845f;   // 1/sqrt(128)
    int buf = 0;

    for (int j = 0; j <= qt; j++) {
        // prefetch next KV tile into registers (overlaps this tile's compute)
        float4 kreg[8], vreg[8];
        bool has_next = (j < qt);
        if (has_next) {
            int nb_base = b * SS + (j + 1) * 64;
#pragma unroll
            for (int it = 0; it < 8; it++) {
                int r = lr + (it << 3);
                const float* kr = &g_qkv[(size_t)(nb_base + r) * QKVN + NH * HD + kvh * HD + (lc4 << 2)];
                kreg[it] = *(const float4*)kr;
                vreg[it] = *(const float4*)(kr + NKV * HD);
            }
        }

        const float* Kb = Ks + buf * KBUF;
        const float* Vb = Vs + buf * VBUF;

        // S = Q @ K^T
        float s4[4][4];
#pragma unroll
        for (int i = 0; i < 4; i++)
#pragma unroll
            for (int jc = 0; jc < 4; jc++) s4[i][jc] = 0.f;

        for (int d4 = 0; d4 < 32; d4++) {
            float4 q[4], k[4];
#pragma unroll
            for (int i = 0; i < 4; i++)
                q[i] = *(const float4*)&Qs[(4 * rg + i) * 128 + (d4 << 2)];
#pragma unroll
            for (int jc = 0; jc < 4; jc++)
                k[jc] = *(const float4*)&Kb[(cg + 16 * jc) * KS_LD + (d4 << 2)];
#pragma unroll
            for (int i = 0; i < 4; i++)
#pragma unroll
                for (int jc = 0; jc < 4; jc++) {
                    s4[i][jc] = fmaf(q[i].x, k[jc].x, s4[i][jc]);
                    s4[i][jc] = fmaf(q[i].y, k[jc].y, s4[i][jc]);
                    s4[i][jc] = fmaf(q[i].z, k[jc].z, s4[i][jc]);
                    s4[i][jc] = fmaf(q[i].w, k[jc].w, s4[i][jc]);
                }
        }

        // scale + causal mask (only diagonal tile needs it)
#pragma unroll
        for (int i = 0; i < 4; i++)
#pragma unroll
            for (int jc = 0; jc < 4; jc++) {
                s4[i][jc] *= scale;
                if (j == qt && (cg + 16 * jc) > (4 * rg + i)) s4[i][jc] = -1e30f;
            }

        // online softmax per row (16-lane butterfly within row group)
#pragma unroll
        for (int i = 0; i < 4; i++) {
            float rm = fmaxf(fmaxf(s4[i][0], s4[i][1]), fmaxf(s4[i][2], s4[i][3]));
#pragma unroll
            for (int off = 8; off; off >>= 1)
                rm = fmaxf(rm, __shfl_xor_sync(0xffffffffu, rm, off));
            float mnew = fmaxf(m_i[i], rm);
            float corr = __expf(m_i[i] - mnew);
            m_i[i] = mnew;

            float rs = 0.f;
#pragma unroll
            for (int jc = 0; jc < 4; jc++) {
                float p = __expf(s4[i][jc] - mnew);
                Ps[(4 * rg + i) * PS_LD + cg + 16 * jc] = p;
                rs += p;
            }
#pragma unroll
            for (int off = 8; off; off >>= 1)
                rs += __shfl_xor_sync(0xffffffffu, rs, off);
            l_i[i] = l_i[i] * corr + rs;
#pragma unroll
            for (int jj = 0; jj < 8; jj++) O[i][jj] *= corr;
        }
        __syncthreads();   // Ps visible to all

        // O += P @ V
        for (int k4 = 0; k4 < 16; k4++) {
            float4 p4[4];
#pragma unroll
            for (int i = 0; i < 4; i++)
                p4[i] = *(const float4*)&Ps[(4 * rg + i) * PS_LD + (k4 << 2)];
#pragma unroll
            for (int kk = 0; kk < 4; kk++) {
                float4 v0 = *(const float4*)&Vb[((k4 << 2) + kk) * 128 + (cg << 2)];
                float4 v1 = *(const float4*)&Vb[((k4 << 2) + kk) * 128 + 64 + (cg << 2)];
#pragma unroll
                for (int i = 0; i < 4; i++) {
                    float p = (&p4[i].x)[kk];
                    O[i][0] = fmaf(p, v0.x, O[i][0]);
                    O[i][1] = fmaf(p, v0.y, O[i][1]);
                    O[i][2] = fmaf(p, v0.z, O[i][2]);
                    O[i][3] = fmaf(p, v0.w, O[i][3]);
                    O[i][4] = fmaf(p, v1.x, O[i][4]);
                    O[i][5] = fmaf(p, v1.y, O[i][5]);
                    O[i][6] = fmaf(p, v1.z, O[i][6]);
                    O[i][7] = fmaf(p, v1.w, O[i][7]);
                }
            }
        }

        // store prefetched tile into the idle buffer
        if (has_next) {
            int nb = buf ^ 1;
            float* Kn = Ks + nb * KBUF;
            float* Vn = Vs + nb * VBUF;
#pragma unroll
            for (int it = 0; it < 8; it++) {
                int r = lr + (it << 3);
                *(float4*)&Kn[r * KS_LD + (lc4 << 2)] = kreg[it];
                *(float4*)&Vn[r * 128   + (lc4 << 2)] = vreg[it];
            }
        }
        __syncthreads();   // next-tile stores visible; Ps safe to overwrite
        buf ^= 1;
    }

    // epilogue: O / l, write to g_attn[row, h*128 + col]
#pragma unroll
    for (int i = 0; i < 4; i++) {
        float inv = 1.0f / l_i[i];
        size_t base = (size_t)(row_base + 4 * rg + i) * (NH * HD) + h * HD;
        float4 o0 = make_float4(O[i][0] * inv, O[i][1] * inv, O[i][2] * inv, O[i][3] * inv);
        float4 o1 = make_float4(O[i][4] * inv, O[i][5] * inv, O[i][6] * inv, O[i][7] * inv);
        *(float4*)&g_attn[base + (cg << 2)]      = o0;
        *(float4*)&g_attn[base + 64 + (cg << 2)] = o1;
    }
}

// ---------------------------------------------------------------------------
extern "C" void kernel_launch(void* const* d_in, const int* in_sizes, int n_in,
                              void* d_out, int out_size)
{
    const float* hidden    = (const float*)d_in[0];
    const int*   positions = (const int*)d_in[1];
    const float* w_qkv     = (const float*)d_in[2];
    const float* w_o       = (const float*)d_in[3];
    float*       out       = (float*)d_out;
    (void)in_sizes; (void)n_in; (void)out_size;

    void *qkv_p = nullptr, *attn_p = nullptr;
    cudaGetSymbolAddress(&qkv_p, g_qkv);
    cudaGetSymbolAddress(&attn_p, g_attn);

    // 1) QKV projection: [4096,2048] @ [2048,4096]
    sgemm128<<<dim3(QKVN / 128, MR / 128), 256>>>(hidden, w_qkv, (float*)qkv_p,
                                                  MR, QKVN, HIDN);

    // 2) RoPE on q & k heads
    rope_kernel<<<(MR * 24 * 64 + 255) / 256, 256>>>(positions);

    // 3) causal GQA flash attention (double-buffered KV)
    cudaFuncSetAttribute(attn_kernel, cudaFuncAttributeMaxDynamicSharedMemorySize,
                         ATTN_SMEM);
    attn_kernel<<<dim3(32, 32), 256, ATTN_SMEM>>>();

    // 4) output projection: [4096,2048] @ [2048,2048]
    sgemm128<<<dim3(HIDN / 128, MR / 128), 256>>>((const float*)attn_p, w_o, out,
                                                  MR, HIDN, NH * HD);
}

// round 12
// speedup vs baseline: 2.5291x; 2.5291x over previous
#include <cuda_runtime.h>
#include <cuda_bf16.h>
#include <math.h>

#define BB   2
#define SS   2048
#define HIDN 2048
#define NH   16
#define NKV  8
#define HD   128
#define QKVN 4096            // (NH + 2*NKV)*HD
#define MR   (BB*SS)         // 4096 rows

// scratch (device globals: no allocations allowed)
__device__ float g_qkv[(size_t)MR * QKVN];       // 64 MB
__device__ float g_attn[(size_t)MR * (NH*HD)];   // 32 MB

// ---------------------------------------------------------------------------
// PTX helpers for bf16 mma.sync path
// ---------------------------------------------------------------------------
#define LDSM4(R, addr)                                                        \
    asm volatile("ldmatrix.sync.aligned.m8n8.x4.shared.b16 {%0,%1,%2,%3}, [%4];" \
        : "=r"((R)[0]), "=r"((R)[1]), "=r"((R)[2]), "=r"((R)[3]) : "r"(addr))

#define LDSM4T(R, addr)                                                       \
    asm volatile("ldmatrix.sync.aligned.m8n8.x4.trans.shared.b16 {%0,%1,%2,%3}, [%4];" \
        : "=r"((R)[0]), "=r"((R)[1]), "=r"((R)[2]), "=r"((R)[3]) : "r"(addr))

#define MMA16816(Cr, Ar, b0_, b1_)                                            \
    asm volatile("mma.sync.aligned.m16n8k16.row.col.f32.bf16.bf16.f32 "       \
        "{%0,%1,%2,%3}, {%4,%5,%6,%7}, {%8,%9}, {%0,%1,%2,%3};"               \
        : "+f"((Cr)[0]), "+f"((Cr)[1]), "+f"((Cr)[2]), "+f"((Cr)[3])          \
        : "r"((Ar)[0]), "r"((Ar)[1]), "r"((Ar)[2]), "r"((Ar)[3]),             \
          "r"(b0_), "r"(b1_))

__device__ __forceinline__ unsigned pack_bf16x2(float x0, float x1)
{
    __nv_bfloat16 b0 = __float2bfloat16_rn(x0);
    __nv_bfloat16 b1 = __float2bfloat16_rn(x1);
    unsigned short u0 = *(unsigned short*)&b0;
    unsigned short u1 = *(unsigned short*)&b1;
    return (unsigned)u0 | ((unsigned)u1 << 16);
}

__device__ __forceinline__ float bf16_round(float x)
{
    return __bfloat162float(__float2bfloat16_rn(x));
}

// ---------------------------------------------------------------------------
// bf16 split-GEMM: C[M,N] = A[M,K] @ B[K,N], fp32 in/out, hi/lo bf16 split,
// 3 mma.sync products (hi*hi + hi*lo + lo*hi), fp32 accumulate.
// 128x128 block tile, 8 warps (2x4), warp tile 64x32, K-chunk 16.
// smem (static, double-buffered): A hi/lo [128][24]bf16 (48B rows),
// B hi/lo [16][136]bf16 (272B rows).
// ---------------------------------------------------------------------------
#define AHI_OFF 0
#define ALO_OFF 6144
#define BHI_OFF 12288
#define BLO_OFF 16640
#define GBUF_B  20992

__global__ __launch_bounds__(256) void bgemm128(
    const float* __restrict__ A, const float* __restrict__ Bm,
    float* __restrict__ C, int M, int N, int K)
{
    __shared__ __align__(16) char gsm[2][GBUF_B];
    int t = threadIdx.x, lane = t & 31, wid = t >> 5;
    int row0 = blockIdx.y << 7, col0 = blockIdx.x << 7;
    int wm = (wid >> 2) << 6, wn = (wid & 3) << 5;

    float acc[16][4];
#pragma unroll
    for (int i = 0; i < 16; i++)
#pragma unroll
        for (int j = 0; j < 4; j++) acc[i][j] = 0.f;

    // staging assignment: A row ar, cols ak..ak+7; B k-row br, cols bn..bn+7
    int ar = t >> 1, ak = (t & 1) << 3;
    int br = t >> 4, bn = (t & 15) << 3;
    const float* Ap = A + (size_t)(row0 + ar) * K + ak;
    const float* Bp = Bm + (size_t)br * N + col0 + bn;

    // ldmatrix per-lane relative byte offsets
    int a_rel = (wm + (lane & 15)) * 48 + ((lane >> 4) << 4);
    int kl = (((lane >> 3) & 1) << 3) + (lane & 7);
    int nl = (lane >> 4) << 3;
    int b_rel = kl * 272 + ((wn + nl) << 1);

    float4 ga0, ga1, gb0, gb1;
    ga0 = *(const float4*)(Ap);
    ga1 = *(const float4*)(Ap + 4);
    gb0 = *(const float4*)(Bp);
    gb1 = *(const float4*)(Bp + 4);

    auto do_sts = [&](char* buf) {
        float va[8] = {ga0.x, ga0.y, ga0.z, ga0.w, ga1.x, ga1.y, ga1.z, ga1.w};
        float vb[8] = {gb0.x, gb0.y, gb0.z, gb0.w, gb1.x, gb1.y, gb1.z, gb1.w};
        unsigned uh[4], ul[4];
#pragma unroll
        for (int i = 0; i < 4; i++) {
            float h0 = bf16_round(va[2 * i]), h1 = bf16_round(va[2 * i + 1]);
            uh[i] = pack_bf16x2(h0, h1);
            ul[i] = pack_bf16x2(va[2 * i] - h0, va[2 * i + 1] - h1);
        }
        *(uint4*)(buf + AHI_OFF + ar * 48 + ak * 2) = make_uint4(uh[0], uh[1], uh[2], uh[3]);
        *(uint4*)(buf + ALO_OFF + ar * 48 + ak * 2) = make_uint4(ul[0], ul[1], ul[2], ul[3]);
#pragma unroll
        for (int i = 0; i < 4; i++) {
            float h0 = bf16_round(vb[2 * i]), h1 = bf16_round(vb[2 * i + 1]);
            uh[i] = pack_bf16x2(h0, h1);
            ul[i] = pack_bf16x2(vb[2 * i] - h0, vb[2 * i + 1] - h1);
        }
        *(uint4*)(buf + BHI_OFF + br * 272 + bn * 2) = make_uint4(uh[0], uh[1], uh[2], uh[3]);
        *(uint4*)(buf + BLO_OFF + br * 272 + bn * 2) = make_uint4(ul[0], ul[1], ul[2], ul[3]);
    };

    auto do_mma = [&](const char* buf) {
        unsigned base = (unsigned)__cvta_generic_to_shared(buf);
        unsigned bh[8], bl[8];
        LDSM4T(bh,     base + BHI_OFF + b_rel);
        LDSM4T(bh + 4, base + BHI_OFF + b_rel + 32);
        LDSM4T(bl,     base + BLO_OFF + b_rel);
        LDSM4T(bl + 4, base + BLO_OFF + b_rel + 32);
#pragma unroll
        for (int mt = 0; mt < 4; mt++) {
            unsigned ah[4], al[4];
            LDSM4(ah, base + AHI_OFF + a_rel + mt * 768);
            LDSM4(al, base + ALO_OFF + a_rel + mt * 768);
#pragma unroll
            for (int nt = 0; nt < 4; nt++) {
                int bi = ((nt >> 1) << 2) + ((nt & 1) << 1);
                float* c = acc[mt * 4 + nt];
                MMA16816(c, ah, bh[bi], bh[bi + 1]);
                MMA16816(c, ah, bl[bi], bl[bi + 1]);
                MMA16816(c, al, bh[bi], bh[bi + 1]);
            }
        }
    };

    do_sts(gsm[0]);
    __syncthreads();

    int buf = 0;
    for (int kc = 0; kc < K; kc += 16) {
        bool hn = (kc + 16) < K;
        if (hn) {
            ga0 = *(const float4*)(Ap + kc + 16);
            ga1 = *(const float4*)(Ap + kc + 20);
            gb0 = *(const float4*)(Bp + (size_t)(kc + 16) * N);
            gb1 = *(const float4*)(Bp + (size_t)(kc + 16) * N + 4);
        }
        do_mma(gsm[buf]);
        if (hn) {
            do_sts(gsm[buf ^ 1]);
            __syncthreads();
            buf ^= 1;
        }
    }

    // epilogue: C fragment m16n8: (c0,c1)->(row, col..col+1), (c2,c3)->(row+8)
#pragma unroll
    for (int mt = 0; mt < 4; mt++)
#pragma unroll
        for (int nt = 0; nt < 4; nt++) {
            int r = row0 + wm + mt * 16 + (lane >> 2);
            int c = col0 + wn + nt * 8 + ((lane & 3) << 1);
            float* cr = acc[mt * 4 + nt];
            *(float2*)(C + (size_t)r * N + c)       = make_float2(cr[0], cr[1]);
            *(float2*)(C + (size_t)(r + 8) * N + c) = make_float2(cr[2], cr[3]);
        }
}

// ---------------------------------------------------------------------------
// RoPE in-place on g_qkv (q heads 0..15 at col h*128, k heads at 2048+h*128)
// ---------------------------------------------------------------------------
__global__ void rope_kernel(const int* __restrict__ positions)
{
    int idx = blockIdx.x * blockDim.x + threadIdx.x;
    const int total = MR * 24 * 64;
    if (idx >= total) return;
    int i    = idx & 63;
    int head = (idx >> 6) % 24;
    int row  = idx / (24 * 64);
    int s    = row & (SS - 1);

    int col = (head < NH) ? head * HD : NH * HD + (head - NH) * HD;

    float e    = (float)(2 * i) * (1.0f / 128.0f);
    float invf = 1.0f / powf(10000.0f, e);
    float fr   = (float)positions[s] * invf;
    float c, sn;
    sincosf(fr, &sn, &c);

    float* p = g_qkv + (size_t)row * QKVN + col;
    float x1 = p[i], x2 = p[i + 64];
    p[i]      = x1 * c - x2 * sn;
    p[i + 64] = x2 * c + x1 * sn;
}

// ---------------------------------------------------------------------------
// Flash attention, causal, GQA (2 q heads per kv head), fp32.
// grid: (32 qtiles [reversed], 32 b*h), 256 threads. Double-buffered KV.
// ---------------------------------------------------------------------------
#define KS_LD   132
#define PS_LD   68
#define KBUF    (64 * KS_LD)
#define VBUF    (64 * 128)
#define ATTN_SMEM ((64*128 + 2*KBUF + 2*VBUF + 64*PS_LD) * 4)  // 183296 B

__global__ __launch_bounds__(256) void attn_kernel()
{
    extern __shared__ float sm[];
    float* Qs = sm;                      // [64][128]
    float* Ks = Qs + 64 * 128;           // [2][64][KS_LD]
    float* Vs = Ks + 2 * KBUF;           // [2][64][128]
    float* Ps = Vs + 2 * VBUF;           // [64][PS_LD]

    int t  = threadIdx.x;
    int rg = t >> 4, cg = t & 15;
    int bh = blockIdx.y;
    int b  = bh >> 4, h = bh & 15;
    int kvh = h >> 1;
    int qt = (int)(gridDim.x - 1) - (int)blockIdx.x;   // heavy tiles first
    int row_base = b * SS + qt * 64;

    int lr = t >> 5, lc4 = t & 31;

    {
        int kv_base = b * SS;            // j = 0
        for (int it = 0; it < 8; it++) {
            int r = lr + (it << 3);
            *(float4*)&Qs[r * 128 + (lc4 << 2)] =
                *(const float4*)&g_qkv[(size_t)(row_base + r) * QKVN + h * HD + (lc4 << 2)];
            const float* kr = &g_qkv[(size_t)(kv_base + r) * QKVN + NH * HD + kvh * HD + (lc4 << 2)];
            *(float4*)&Ks[r * KS_LD + (lc4 << 2)] = *(const float4*)kr;
            *(float4*)&Vs[r * 128   + (lc4 << 2)] = *(const float4*)(kr + NKV * HD);
        }
    }
    __syncthreads();

    float m_i[4], l_i[4], O[4][8];
#pragma unroll
    for (int i = 0; i < 4; i++) {
        m_i[i] = -1e30f; l_i[i] = 0.f;
#pragma unroll
        for (int j = 0; j < 8; j++) O[i][j] = 0.f;
    }

    const float scale = 0.08838834764831845f;   // 1/sqrt(128)
    int buf = 0;

    for (int j = 0; j <= qt; j++) {
        float4 kreg[8], vreg[8];
        bool has_next = (j < qt);
        if (has_next) {
            int nb_base = b * SS + (j + 1) * 64;
#pragma unroll
            for (int it = 0; it < 8; it++) {
                int r = lr + (it << 3);
                const float* kr = &g_qkv[(size_t)(nb_base + r) * QKVN + NH * HD + kvh * HD + (lc4 << 2)];
                kreg[it] = *(const float4*)kr;
                vreg[it] = *(const float4*)(kr + NKV * HD);
            }
        }

        const float* Kb = Ks + buf * KBUF;
        const float* Vb = Vs + buf * VBUF;

        float s4[4][4];
#pragma unroll
        for (int i = 0; i < 4; i++)
#pragma unroll
            for (int jc = 0; jc < 4; jc++) s4[i][jc] = 0.f;

        for (int d4 = 0; d4 < 32; d4++) {
            float4 q[4], k[4];
#pragma unroll
            for (int i = 0; i < 4; i++)
                q[i] = *(const float4*)&Qs[(4 * rg + i) * 128 + (d4 << 2)];
#pragma unroll
            for (int jc = 0; jc < 4; jc++)
                k[jc] = *(const float4*)&Kb[(cg + 16 * jc) * KS_LD + (d4 << 2)];
#pragma unroll
            for (int i = 0; i < 4; i++)
#pragma unroll
                for (int jc = 0; jc < 4; jc++) {
                    s4[i][jc] = fmaf(q[i].x, k[jc].x, s4[i][jc]);
                    s4[i][jc] = fmaf(q[i].y, k[jc].y, s4[i][jc]);
                    s4[i][jc] = fmaf(q[i].z, k[jc].z, s4[i][jc]);
                    s4[i][jc] = fmaf(q[i].w, k[jc].w, s4[i][jc]);
                }
        }

#pragma unroll
        for (int i = 0; i < 4; i++)
#pragma unroll
            for (int jc = 0; jc < 4; jc++) {
                s4[i][jc] *= scale;
                if (j == qt && (cg + 16 * jc) > (4 * rg + i)) s4[i][jc] = -1e30f;
            }

#pragma unroll
        for (int i = 0; i < 4; i++) {
            float rm = fmaxf(fmaxf(s4[i][0], s4[i][1]), fmaxf(s4[i][2], s4[i][3]));
#pragma unroll
            for (int off = 8; off; off >>= 1)
                rm = fmaxf(rm, __shfl_xor_sync(0xffffffffu, rm, off));
            float mnew = fmaxf(m_i[i], rm);
            float corr = __expf(m_i[i] - mnew);
            m_i[i] = mnew;

            float rs = 0.f;
#pragma unroll
            for (int jc = 0; jc < 4; jc++) {
                float p = __expf(s4[i][jc] - mnew);
                Ps[(4 * rg + i) * PS_LD + cg + 16 * jc] = p;
                rs += p;
            }
#pragma unroll
            for (int off = 8; off; off >>= 1)
                rs += __shfl_xor_sync(0xffffffffu, rs, off);
            l_i[i] = l_i[i] * corr + rs;
#pragma unroll
            for (int jj = 0; jj < 8; jj++) O[i][jj] *= corr;
        }
        __syncthreads();

        for (int k4 = 0; k4 < 16; k4++) {
            float4 p4[4];
#pragma unroll
            for (int i = 0; i < 4; i++)
                p4[i] = *(const float4*)&Ps[(4 * rg + i) * PS_LD + (k4 << 2)];
#pragma unroll
            for (int kk = 0; kk < 4; kk++) {
                float4 v0 = *(const float4*)&Vb[((k4 << 2) + kk) * 128 + (cg << 2)];
                float4 v1 = *(const float4*)&Vb[((k4 << 2) + kk) * 128 + 64 + (cg << 2)];
#pragma unroll
                for (int i = 0; i < 4; i++) {
                    float p = (&p4[i].x)[kk];
                    O[i][0] = fmaf(p, v0.x, O[i][0]);
                    O[i][1] = fmaf(p, v0.y, O[i][1]);
                    O[i][2] = fmaf(p, v0.z, O[i][2]);
                    O[i][3] = fmaf(p, v0.w, O[i][3]);
                    O[i][4] = fmaf(p, v1.x, O[i][4]);
                    O[i][5] = fmaf(p, v1.y, O[i][5]);
                    O[i][6] = fmaf(p, v1.z, O[i][6]);
                    O[i][7] = fmaf(p, v1.w, O[i][7]);
                }
            }
        }

        if (has_next) {
            int nb = buf ^ 1;
            float* Kn = Ks + nb * KBUF;
            float* Vn = Vs + nb * VBUF;
#pragma unroll
            for (int it = 0; it < 8; it++) {
                int r = lr + (it << 3);
                *(float4*)&Kn[r * KS_LD + (lc4 << 2)] = kreg[it];
                *(float4*)&Vn[r * 128   + (lc4 << 2)] = vreg[it];
            }
        }
        __syncthreads();
        buf ^= 1;
    }

#pragma unroll
    for (int i = 0; i < 4; i++) {
        float inv = 1.0f / l_i[i];
        size_t base = (size_t)(row_base + 4 * rg + i) * (NH * HD) + h * HD;
        float4 o0 = make_float4(O[i][0] * inv, O[i][1] * inv, O[i][2] * inv, O[i][3] * inv);
        float4 o1 = make_float4(O[i][4] * inv, O[i][5] * inv, O[i][6] * inv, O[i][7] * inv);
        *(float4*)&g_attn[base + (cg << 2)]      = o0;
        *(float4*)&g_attn[base + 64 + (cg << 2)] = o1;
    }
}

// ---------------------------------------------------------------------------
extern "C" void kernel_launch(void* const* d_in, const int* in_sizes, int n_in,
                              void* d_out, int out_size)
{
    const float* hidden    = (const float*)d_in[0];
    const int*   positions = (const int*)d_in[1];
    const float* w_qkv     = (const float*)d_in[2];
    const float* w_o       = (const float*)d_in[3];
    float*       out       = (float*)d_out;
    (void)in_sizes; (void)n_in; (void)out_size;

    void *qkv_p = nullptr, *attn_p = nullptr;
    cudaGetSymbolAddress(&qkv_p, g_qkv);
    cudaGetSymbolAddress(&attn_p, g_attn);

    // 1) QKV projection: [4096,2048] @ [2048,4096]  (tensor-core split-bf16)
    bgemm128<<<dim3(QKVN / 128, MR / 128), 256>>>(hidden, w_qkv, (float*)qkv_p,
                                                  MR, QKVN, HIDN);

    // 2) RoPE on q & k heads
    rope_kernel<<<(MR * 24 * 64 + 255) / 256, 256>>>(positions);

    // 3) causal GQA flash attention (double-buffered KV, fp32)
    cudaFuncSetAttribute(attn_kernel, cudaFuncAttributeMaxDynamicSharedMemorySize,
                         ATTN_SMEM);
    attn_kernel<<<dim3(32, 32), 256, ATTN_SMEM>>>();

    // 4) output projection: [4096,2048] @ [2048,2048]  (tensor-core split-bf16)
    bgemm128<<<dim3(HIDN / 128, MR / 128), 256>>>((const float*)attn_p, w_o, out,
                                                  MR, HIDN, NH * HD);
}

// round 14
// speedup vs baseline: 3.3229x; 1.3138x over previous
#include <cuda_runtime.h>
#include <cuda_bf16.h>
#include <math.h>

#define BB   2
#define SS   2048
#define HIDN 2048
#define NH   16
#define NKV  8
#define HD   128
#define QKVN 4096            // (NH + 2*NKV)*HD
#define MR   (BB*SS)         // 4096 rows

// scratch (device globals: no allocations allowed)
__device__ float g_qkv[(size_t)MR * QKVN];       // 64 MB
__device__ float g_attn[(size_t)MR * (NH*HD)];   // 32 MB

// ---------------------------------------------------------------------------
// PTX helpers for bf16 mma.sync path
// ---------------------------------------------------------------------------
#define LDSM4(R, addr)                                                        \
    asm volatile("ldmatrix.sync.aligned.m8n8.x4.shared.b16 {%0,%1,%2,%3}, [%4];" \
        : "=r"((R)[0]), "=r"((R)[1]), "=r"((R)[2]), "=r"((R)[3]) : "r"(addr))

#define LDSM4T(R, addr)                                                       \
    asm volatile("ldmatrix.sync.aligned.m8n8.x4.trans.shared.b16 {%0,%1,%2,%3}, [%4];" \
        : "=r"((R)[0]), "=r"((R)[1]), "=r"((R)[2]), "=r"((R)[3]) : "r"(addr))

#define MMA16816(Cr, Ar, b0_, b1_)                                            \
    asm volatile("mma.sync.aligned.m16n8k16.row.col.f32.bf16.bf16.f32 "       \
        "{%0,%1,%2,%3}, {%4,%5,%6,%7}, {%8,%9}, {%0,%1,%2,%3};"               \
        : "+f"((Cr)[0]), "+f"((Cr)[1]), "+f"((Cr)[2]), "+f"((Cr)[3])          \
        : "r"((Ar)[0]), "r"((Ar)[1]), "r"((Ar)[2]), "r"((Ar)[3]),             \
          "r"(b0_), "r"(b1_))

__device__ __forceinline__ unsigned pack_bf16x2(float x0, float x1)
{
    __nv_bfloat16 b0 = __float2bfloat16_rn(x0);
    __nv_bfloat16 b1 = __float2bfloat16_rn(x1);
    unsigned short u0 = *(unsigned short*)&b0;
    unsigned short u1 = *(unsigned short*)&b1;
    return (unsigned)u0 | ((unsigned)u1 << 16);
}

__device__ __forceinline__ float bf16_round(float x)
{
    return __bfloat162float(__float2bfloat16_rn(x));
}

// ---------------------------------------------------------------------------
// bf16 split-GEMM (verified R12): C = A @ B, hi/lo split, 3 mma products.
// ---------------------------------------------------------------------------
#define AHI_OFF 0
#define ALO_OFF 6144
#define BHI_OFF 12288
#define BLO_OFF 16640
#define GBUF_B  20992

__global__ __launch_bounds__(256) void bgemm128(
    const float* __restrict__ A, const float* __restrict__ Bm,
    float* __restrict__ C, int M, int N, int K)
{
    __shared__ __align__(16) char gsm[2][GBUF_B];
    int t = threadIdx.x, lane = t & 31, wid = t >> 5;
    int row0 = blockIdx.y << 7, col0 = blockIdx.x << 7;
    int wm = (wid >> 2) << 6, wn = (wid & 3) << 5;

    float acc[16][4];
#pragma unroll
    for (int i = 0; i < 16; i++)
#pragma unroll
        for (int j = 0; j < 4; j++) acc[i][j] = 0.f;

    int ar = t >> 1, ak = (t & 1) << 3;
    int br = t >> 4, bn = (t & 15) << 3;
    const float* Ap = A + (size_t)(row0 + ar) * K + ak;
    const float* Bp = Bm + (size_t)br * N + col0 + bn;

    int a_rel = (wm + (lane & 15)) * 48 + ((lane >> 4) << 4);
    int kl = (((lane >> 3) & 1) << 3) + (lane & 7);
    int nl = (lane >> 4) << 3;
    int b_rel = kl * 272 + ((wn + nl) << 1);

    float4 ga0, ga1, gb0, gb1;
    ga0 = *(const float4*)(Ap);
    ga1 = *(const float4*)(Ap + 4);
    gb0 = *(const float4*)(Bp);
    gb1 = *(const float4*)(Bp + 4);

    auto do_sts = [&](char* buf) {
        float va[8] = {ga0.x, ga0.y, ga0.z, ga0.w, ga1.x, ga1.y, ga1.z, ga1.w};
        float vb[8] = {gb0.x, gb0.y, gb0.z, gb0.w, gb1.x, gb1.y, gb1.z, gb1.w};
        unsigned uh[4], ul[4];
#pragma unroll
        for (int i = 0; i < 4; i++) {
            float h0 = bf16_round(va[2 * i]), h1 = bf16_round(va[2 * i + 1]);
            uh[i] = pack_bf16x2(h0, h1);
            ul[i] = pack_bf16x2(va[2 * i] - h0, va[2 * i + 1] - h1);
        }
        *(uint4*)(buf + AHI_OFF + ar * 48 + ak * 2) = make_uint4(uh[0], uh[1], uh[2], uh[3]);
        *(uint4*)(buf + ALO_OFF + ar * 48 + ak * 2) = make_uint4(ul[0], ul[1], ul[2], ul[3]);
#pragma unroll
        for (int i = 0; i < 4; i++) {
            float h0 = bf16_round(vb[2 * i]), h1 = bf16_round(vb[2 * i + 1]);
            uh[i] = pack_bf16x2(h0, h1);
            ul[i] = pack_bf16x2(vb[2 * i] - h0, vb[2 * i + 1] - h1);
        }
        *(uint4*)(buf + BHI_OFF + br * 272 + bn * 2) = make_uint4(uh[0], uh[1], uh[2], uh[3]);
        *(uint4*)(buf + BLO_OFF + br * 272 + bn * 2) = make_uint4(ul[0], ul[1], ul[2], ul[3]);
    };

    auto do_mma = [&](const char* buf) {
        unsigned base = (unsigned)__cvta_generic_to_shared(buf);
        unsigned bh[8], bl[8];
        LDSM4T(bh,     base + BHI_OFF + b_rel);
        LDSM4T(bh + 4, base + BHI_OFF + b_rel + 32);
        LDSM4T(bl,     base + BLO_OFF + b_rel);
        LDSM4T(bl + 4, base + BLO_OFF + b_rel + 32);
#pragma unroll
        for (int mt = 0; mt < 4; mt++) {
            unsigned ah[4], al[4];
            LDSM4(ah, base + AHI_OFF + a_rel + mt * 768);
            LDSM4(al, base + ALO_OFF + a_rel + mt * 768);
#pragma unroll
            for (int nt = 0; nt < 4; nt++) {
                int bi = ((nt >> 1) << 2) + ((nt & 1) << 1);
                float* c = acc[mt * 4 + nt];
                MMA16816(c, ah, bh[bi], bh[bi + 1]);
                MMA16816(c, ah, bl[bi], bl[bi + 1]);
                MMA16816(c, al, bh[bi], bh[bi + 1]);
            }
        }
    };

    do_sts(gsm[0]);
    __syncthreads();

    int buf = 0;
    for (int kc = 0; kc < K; kc += 16) {
        bool hn = (kc + 16) < K;
        if (hn) {
            ga0 = *(const float4*)(Ap + kc + 16);
            ga1 = *(const float4*)(Ap + kc + 20);
            gb0 = *(const float4*)(Bp + (size_t)(kc + 16) * N);
            gb1 = *(const float4*)(Bp + (size_t)(kc + 16) * N + 4);
        }
        do_mma(gsm[buf]);
        if (hn) {
            do_sts(gsm[buf ^ 1]);
            __syncthreads();
            buf ^= 1;
        }
    }

#pragma unroll
    for (int mt = 0; mt < 4; mt++)
#pragma unroll
        for (int nt = 0; nt < 4; nt++) {
            int r = row0 + wm + mt * 16 + (lane >> 2);
            int c = col0 + wn + nt * 8 + ((lane & 3) << 1);
            float* cr = acc[mt * 4 + nt];
            *(float2*)(C + (size_t)r * N + c)       = make_float2(cr[0], cr[1]);
            *(float2*)(C + (size_t)(r + 8) * N + c) = make_float2(cr[2], cr[3]);
        }
}

// ---------------------------------------------------------------------------
// RoPE in-place on g_qkv
// ---------------------------------------------------------------------------
__global__ void rope_kernel(const int* __restrict__ positions)
{
    int idx = blockIdx.x * blockDim.x + threadIdx.x;
    const int total = MR * 24 * 64;
    if (idx >= total) return;
    int i    = idx & 63;
    int head = (idx >> 6) % 24;
    int row  = idx / (24 * 64);
    int s    = row & (SS - 1);

    int col = (head < NH) ? head * HD : NH * HD + (head - NH) * HD;

    float e    = (float)(2 * i) * (1.0f / 128.0f);
    float invf = 1.0f / powf(10000.0f, e);
    float fr   = (float)positions[s] * invf;
    float c, sn;
    sincosf(fr, &sn, &c);

    float* p = g_qkv + (size_t)row * QKVN + col;
    float x1 = p[i], x2 = p[i + 64];
    p[i]      = x1 * c - x2 * sn;
    p[i + 64] = x2 * c + x1 * sn;
}

// ---------------------------------------------------------------------------
// Flash attention on tensor cores: hi/lo split mma for S=QK^T and O=PV.
// BM=128 q rows (8 warps x 16 rows), BN=64 keys/iter.
// Warp owns complete score rows -> softmax warp-local (4-lane shfl).
// Q pre-scaled+split staged once; K/V split-staged per iter.
// All rows padded to 272B (LDSM conflict-free).
// ---------------------------------------------------------------------------
#define QHI_O 0
#define QLO_O 34816
#define KHI_O 69632
#define KLO_O 87040
#define VHI_O 104448
#define VLO_O 121856
#define ATTN2_SMEM 139264

__global__ __launch_bounds__(256) void attn_mma()
{
    extern __shared__ char dynsm[];
    unsigned sbase = (unsigned)__cvta_generic_to_shared(dynsm);
    int t = threadIdx.x, lane = t & 31, wid = t >> 5;
    int bh = blockIdx.y, b = bh >> 4, h = bh & 15, kvh = h >> 1;
    int qt = (int)(gridDim.x - 1) - (int)blockIdx.x;   // heavy tiles first
    int row_base = b * SS + qt * 128;                  // global memory row
    int seq_base = qt * 128;                           // sequence position

    const float scale = 0.08838834764831845f;          // 1/sqrt(128)

    // stage Q (scaled, hi/lo split), 2 threads per row
    {
        int r  = t >> 1;
        int c0 = (t & 1) << 6;
        const float* qp = &g_qkv[(size_t)(row_base + r) * QKVN + h * HD];
        char* qh = dynsm + QHI_O + r * 272;
        char* ql = dynsm + QLO_O + r * 272;
#pragma unroll
        for (int i = 0; i < 16; i++) {
            int c = c0 + (i << 2);
            float4 v = *(const float4*)(qp + c);
            v.x *= scale; v.y *= scale; v.z *= scale; v.w *= scale;
            float hx = bf16_round(v.x), hy = bf16_round(v.y);
            float hz = bf16_round(v.z), hw = bf16_round(v.w);
            *(uint2*)(qh + c * 2) = make_uint2(pack_bf16x2(hx, hy), pack_bf16x2(hz, hw));
            *(uint2*)(ql + c * 2) = make_uint2(pack_bf16x2(v.x - hx, v.y - hy),
                                               pack_bf16x2(v.z - hz, v.w - hw));
        }
    }

    float o[16][4];
#pragma unroll
    for (int i = 0; i < 16; i++)
#pragma unroll
        for (int j = 0; j < 4; j++) o[i][j] = 0.f;
    float m2[2] = {-1e30f, -1e30f}, l2[2] = {0.f, 0.f};

    int wr_seq = seq_base + (wid << 4);
    int n_kv = 2 * (qt + 1);

    // per-lane ldsm offsets
    int qa_rel  = ((wid << 4) + (lane & 15)) * 272 + ((lane >> 4) << 4);  // + kc*32
    int kb_key  = ((lane >> 4) << 3) + (lane & 7);                         // + np*16
    int kb_byte = ((lane >> 3) & 1) << 4;                                  // + kc*32
    int v_kl    = (((lane >> 3) & 1) << 3) + (lane & 7);                   // + kc*16
    int v_n     = (lane >> 4) << 3;                                        // + ntp*16

    for (int j = 0; j < n_kv; j++) {
        __syncthreads();                       // prev iter reads done
        int kv_base = j << 6;
        // stage K/V (hi/lo split), 4 threads per key-row
        {
            int r = t >> 2, c0 = (t & 3) << 5;
            const float* kp = &g_qkv[(size_t)(b * SS + kv_base + r) * QKVN + NH * HD + kvh * HD];
            const float* vp = kp + NKV * HD;
            char* kh = dynsm + KHI_O + r * 272;
            char* klo = dynsm + KLO_O + r * 272;
            char* vh = dynsm + VHI_O + r * 272;
            char* vlo = dynsm + VLO_O + r * 272;
#pragma unroll
            for (int i = 0; i < 8; i++) {
                int c = c0 + (i << 2);
                float4 k4 = *(const float4*)(kp + c);
                float hx = bf16_round(k4.x), hy = bf16_round(k4.y);
                float hz = bf16_round(k4.z), hw = bf16_round(k4.w);
                *(uint2*)(kh + c * 2)  = make_uint2(pack_bf16x2(hx, hy), pack_bf16x2(hz, hw));
                *(uint2*)(klo + c * 2) = make_uint2(pack_bf16x2(k4.x - hx, k4.y - hy),
                                                    pack_bf16x2(k4.z - hz, k4.w - hw));
                float4 v4 = *(const float4*)(vp + c);
                hx = bf16_round(v4.x); hy = bf16_round(v4.y);
                hz = bf16_round(v4.z); hw = bf16_round(v4.w);
                *(uint2*)(vh + c * 2)  = make_uint2(pack_bf16x2(hx, hy), pack_bf16x2(hz, hw));
                *(uint2*)(vlo + c * 2) = make_uint2(pack_bf16x2(v4.x - hx, v4.y - hy),
                                                    pack_bf16x2(v4.z - hz, v4.w - hw));
            }
        }
        __syncthreads();

        // S = Q*K^T (split: hi*hi + hi*lo + lo*hi)
        float s[8][4];
#pragma unroll
        for (int i = 0; i < 8; i++)
#pragma unroll
            for (int jj = 0; jj < 4; jj++) s[i][jj] = 0.f;

#pragma unroll
        for (int kc = 0; kc < 8; kc++) {
            unsigned aqh[4], aql[4];
            LDSM4(aqh, sbase + QHI_O + qa_rel + kc * 32);
            LDSM4(aql, sbase + QLO_O + qa_rel + kc * 32);
#pragma unroll
            for (int np = 0; np < 4; np++) {
                unsigned kbh[4], kbl[4];
                unsigned koff = (unsigned)((kb_key + np * 16) * 272 + kb_byte + kc * 32);
                LDSM4(kbh, sbase + KHI_O + koff);
                LDSM4(kbl, sbase + KLO_O + koff);
                MMA16816(s[2 * np],     aqh, kbh[0], kbh[1]);
                MMA16816(s[2 * np],     aqh, kbl[0], kbl[1]);
                MMA16816(s[2 * np],     aql, kbh[0], kbh[1]);
                MMA16816(s[2 * np + 1], aqh, kbh[2], kbh[3]);
                MMA16816(s[2 * np + 1], aqh, kbl[2], kbl[3]);
                MMA16816(s[2 * np + 1], aql, kbh[2], kbh[3]);
            }
        }

        // causal mask (only near diagonal)
        if (kv_base + 63 > wr_seq) {
            int r0 = wr_seq + (lane >> 2), r1 = r0 + 8;
#pragma unroll
            for (int nt = 0; nt < 8; nt++) {
                int cgl = kv_base + nt * 8 + ((lane & 3) << 1);
                if (cgl     > r0) s[nt][0] = -1e30f;
                if (cgl + 1 > r0) s[nt][1] = -1e30f;
                if (cgl     > r1) s[nt][2] = -1e30f;
                if (cgl + 1 > r1) s[nt][3] = -1e30f;
            }
        }

        // online softmax (rows r0, r1 per thread; 4-lane row groups)
        float mx0 = -1e30f, mx1 = -1e30f;
#pragma unroll
        for (int nt = 0; nt < 8; nt++) {
            mx0 = fmaxf(mx0, fmaxf(s[nt][0], s[nt][1]));
            mx1 = fmaxf(mx1, fmaxf(s[nt][2], s[nt][3]));
        }
        mx0 = fmaxf(mx0, __shfl_xor_sync(0xffffffffu, mx0, 1));
        mx0 = fmaxf(mx0, __shfl_xor_sync(0xffffffffu, mx0, 2));
        mx1 = fmaxf(mx1, __shfl_xor_sync(0xffffffffu, mx1, 1));
        mx1 = fmaxf(mx1, __shfl_xor_sync(0xffffffffu, mx1, 2));
        float mn0 = fmaxf(m2[0], mx0), mn1 = fmaxf(m2[1], mx1);
        float cr0 = __expf(m2[0] - mn0), cr1 = __expf(m2[1] - mn1);
        m2[0] = mn0; m2[1] = mn1;
        float rs0 = 0.f, rs1 = 0.f;
#pragma unroll
        for (int nt = 0; nt < 8; nt++) {
            s[nt][0] = __expf(s[nt][0] - mn0);
            s[nt][1] = __expf(s[nt][1] - mn0);
            s[nt][2] = __expf(s[nt][2] - mn1);
            s[nt][3] = __expf(s[nt][3] - mn1);
            rs0 += s[nt][0] + s[nt][1];
            rs1 += s[nt][2] + s[nt][3];
        }
        rs0 += __shfl_xor_sync(0xffffffffu, rs0, 1);
        rs0 += __shfl_xor_sync(0xffffffffu, rs0, 2);
        rs1 += __shfl_xor_sync(0xffffffffu, rs1, 1);
        rs1 += __shfl_xor_sync(0xffffffffu, rs1, 2);
        l2[0] = l2[0] * cr0 + rs0;
        l2[1] = l2[1] * cr1 + rs1;
#pragma unroll
        for (int nt = 0; nt < 16; nt++) {
            o[nt][0] *= cr0; o[nt][1] *= cr0;
            o[nt][2] *= cr1; o[nt][3] *= cr1;
        }

        // O += P*V (split: Ph*Vh + Pl*Vh + Ph*Vl); P frags register-converted
#pragma unroll
        for (int kc = 0; kc < 4; kc++) {
            unsigned aph[4], apl[4];
            {
                float p00 = s[2 * kc][0],     p01 = s[2 * kc][1];
                float p10 = s[2 * kc][2],     p11 = s[2 * kc][3];
                float q00 = s[2 * kc + 1][0], q01 = s[2 * kc + 1][1];
                float q10 = s[2 * kc + 1][2], q11 = s[2 * kc + 1][3];
                float h00 = bf16_round(p00), h01 = bf16_round(p01);
                float h10 = bf16_round(p10), h11 = bf16_round(p11);
                float g00 = bf16_round(q00), g01 = bf16_round(q01);
                float g10 = bf16_round(q10), g11 = bf16_round(q11);
                aph[0] = pack_bf16x2(h00, h01); aph[1] = pack_bf16x2(h10, h11);
                aph[2] = pack_bf16x2(g00, g01); aph[3] = pack_bf16x2(g10, g11);
                apl[0] = pack_bf16x2(p00 - h00, p01 - h01);
                apl[1] = pack_bf16x2(p10 - h10, p11 - h11);
                apl[2] = pack_bf16x2(q00 - g00, q01 - g01);
                apl[3] = pack_bf16x2(q10 - g10, q11 - g11);
            }
#pragma unroll
            for (int ntp = 0; ntp < 8; ntp++) {
                unsigned vbh[4], vbl[4];
                unsigned voff = (unsigned)((kc * 16 + v_kl) * 272 + (ntp * 16 + v_n) * 2);
                LDSM4T(vbh, sbase + VHI_O + voff);
                LDSM4T(vbl, sbase + VLO_O + voff);
                MMA16816(o[2 * ntp],     aph, vbh[0], vbh[1]);
                MMA16816(o[2 * ntp],     apl, vbh[0], vbh[1]);
                MMA16816(o[2 * ntp],     aph, vbl[0], vbl[1]);
                MMA16816(o[2 * ntp + 1], aph, vbh[2], vbh[3]);
                MMA16816(o[2 * ntp + 1], apl, vbh[2], vbh[3]);
                MMA16816(o[2 * ntp + 1], aph, vbl[2], vbl[3]);
            }
        }
    }

    // epilogue: O/l -> g_attn
    float inv0 = 1.f / l2[0], inv1 = 1.f / l2[1];
    int r0 = row_base + (wid << 4) + (lane >> 2);
#pragma unroll
    for (int nt = 0; nt < 16; nt++) {
        int c = h * HD + nt * 8 + ((lane & 3) << 1);
        *(float2*)&g_attn[(size_t)r0 * (NH * HD) + c] =
            make_float2(o[nt][0] * inv0, o[nt][1] * inv0);
        *(float2*)&g_attn[(size_t)(r0 + 8) * (NH * HD) + c] =
            make_float2(o[nt][2] * inv1, o[nt][3] * inv1);
    }
}

// ---------------------------------------------------------------------------
extern "C" void kernel_launch(void* const* d_in, const int* in_sizes, int n_in,
                              void* d_out, int out_size)
{
    const float* hidden    = (const float*)d_in[0];
    const int*   positions = (const int*)d_in[1];
    const float* w_qkv     = (const float*)d_in[2];
    const float* w_o       = (const float*)d_in[3];
    float*       out       = (float*)d_out;
    (void)in_sizes; (void)n_in; (void)out_size;

    void *qkv_p = nullptr, *attn_p = nullptr;
    cudaGetSymbolAddress(&qkv_p, g_qkv);
    cudaGetSymbolAddress(&attn_p, g_attn);

    // 1) QKV projection (tensor-core split-bf16)
    bgemm128<<<dim3(QKVN / 128, MR / 128), 256>>>(hidden, w_qkv, (float*)qkv_p,
                                                  MR, QKVN, HIDN);

    // 2) RoPE
    rope_kernel<<<(MR * 24 * 64 + 255) / 256, 256>>>(positions);

    // 3) causal GQA flash attention (tensor-core split-bf16)
    cudaFuncSetAttribute(attn_mma, cudaFuncAttributeMaxDynamicSharedMemorySize,
                         ATTN2_SMEM);
    attn_mma<<<dim3(SS / 128, 32), 256, ATTN2_SMEM>>>();

    // 4) output projection (tensor-core split-bf16)
    bgemm128<<<dim3(HIDN / 128, MR / 128), 256>>>((const float*)attn_p, w_o, out,
                                                  MR, HIDN, NH * HD);
}

// round 17
// speedup vs baseline: 3.5015x; 1.0538x over previous
#include <cuda_runtime.h>
#include <cuda_bf16.h>
#include <math.h>

#define BB   2
#define SS   2048
#define HIDN 2048
#define NH   16
#define NKV  8
#define HD   128
#define QKVN 4096            // (NH + 2*NKV)*HD
#define MR   (BB*SS)         // 4096 rows

// scratch (device globals: no allocations allowed)
__device__ float g_qkv[(size_t)MR * QKVN];       // 64 MB
__device__ float g_attn[(size_t)MR * (NH*HD)];   // 32 MB
// pre-split K/V planes: [0]=Khi [1]=Klo [2]=Vhi [3]=Vlo, bf16x2 packed
#define KVS_N (BB * NKV * SS * 64)
__device__ unsigned g_kvs[4][KVS_N];             // 32 MB

// ---------------------------------------------------------------------------
// PTX helpers
// ---------------------------------------------------------------------------
#define LDSM4(R, addr)                                                        \
    asm volatile("ldmatrix.sync.aligned.m8n8.x4.shared.b16 {%0,%1,%2,%3}, [%4];" \
        : "=r"((R)[0]), "=r"((R)[1]), "=r"((R)[2]), "=r"((R)[3]) : "r"(addr))

#define LDSM4T(R, addr)                                                       \
    asm volatile("ldmatrix.sync.aligned.m8n8.x4.trans.shared.b16 {%0,%1,%2,%3}, [%4];" \
        : "=r"((R)[0]), "=r"((R)[1]), "=r"((R)[2]), "=r"((R)[3]) : "r"(addr))

#define MMA16816(Cr, Ar, b0_, b1_)                                            \
    asm volatile("mma.sync.aligned.m16n8k16.row.col.f32.bf16.bf16.f32 "       \
        "{%0,%1,%2,%3}, {%4,%5,%6,%7}, {%8,%9}, {%0,%1,%2,%3};"               \
        : "+f"((Cr)[0]), "+f"((Cr)[1]), "+f"((Cr)[2]), "+f"((Cr)[3])          \
        : "r"((Ar)[0]), "r"((Ar)[1]), "r"((Ar)[2]), "r"((Ar)[3]),             \
          "r"(b0_), "r"(b1_))

#define CPASYNC(dst, src)                                                     \
    asm volatile("cp.async.cg.shared.global [%0], [%1], 16;"                  \
        :: "r"(dst), "l"(src))
#define CPCOMMIT() asm volatile("cp.async.commit_group;" ::: "memory")
#define CPWAIT0()  asm volatile("cp.async.wait_group 0;" ::: "memory")

__device__ __forceinline__ unsigned pack_bf16x2(float x0, float x1)
{
    __nv_bfloat16 b0 = __float2bfloat16_rn(x0);
    __nv_bfloat16 b1 = __float2bfloat16_rn(x1);
    unsigned short u0 = *(unsigned short*)&b0;
    unsigned short u1 = *(unsigned short*)&b1;
    return (unsigned)u0 | ((unsigned)u1 << 16);
}

__device__ __forceinline__ float bf16_round(float x)
{
    return __bfloat162float(__float2bfloat16_rn(x));
}

// ---------------------------------------------------------------------------
// bf16 split-GEMM (verified R12): C = A @ B, hi/lo split, 3 mma products.
// ---------------------------------------------------------------------------
#define AHI_OFF 0
#define ALO_OFF 6144
#define BHI_OFF 12288
#define BLO_OFF 16640
#define GBUF_B  20992

__global__ __launch_bounds__(256) void bgemm128(
    const float* __restrict__ A, const float* __restrict__ Bm,
    float* __restrict__ C, int M, int N, int K)
{
    __shared__ __align__(16) char gsm[2][GBUF_B];
    int t = threadIdx.x, lane = t & 31, wid = t >> 5;
    int row0 = blockIdx.y << 7, col0 = blockIdx.x << 7;
    int wm = (wid >> 2) << 6, wn = (wid & 3) << 5;

    float acc[16][4];
#pragma unroll
    for (int i = 0; i < 16; i++)
#pragma unroll
        for (int j = 0; j < 4; j++) acc[i][j] = 0.f;

    int ar = t >> 1, ak = (t & 1) << 3;
    int br = t >> 4, bn = (t & 15) << 3;
    const float* Ap = A + (size_t)(row0 + ar) * K + ak;
    const float* Bp = Bm + (size_t)br * N + col0 + bn;

    int a_rel = (wm + (lane & 15)) * 48 + ((lane >> 4) << 4);
    int kl = (((lane >> 3) & 1) << 3) + (lane & 7);
    int nl = (lane >> 4) << 3;
    int b_rel = kl * 272 + ((wn + nl) << 1);

    float4 ga0, ga1, gb0, gb1;
    ga0 = *(const float4*)(Ap);
    ga1 = *(const float4*)(Ap + 4);
    gb0 = *(const float4*)(Bp);
    gb1 = *(const float4*)(Bp + 4);

    auto do_sts = [&](char* buf) {
        float va[8] = {ga0.x, ga0.y, ga0.z, ga0.w, ga1.x, ga1.y, ga1.z, ga1.w};
        float vb[8] = {gb0.x, gb0.y, gb0.z, gb0.w, gb1.x, gb1.y, gb1.z, gb1.w};
        unsigned uh[4], ul[4];
#pragma unroll
        for (int i = 0; i < 4; i++) {
            float h0 = bf16_round(va[2 * i]), h1 = bf16_round(va[2 * i + 1]);
            uh[i] = pack_bf16x2(h0, h1);
            ul[i] = pack_bf16x2(va[2 * i] - h0, va[2 * i + 1] - h1);
        }
        *(uint4*)(buf + AHI_OFF + ar * 48 + ak * 2) = make_uint4(uh[0], uh[1], uh[2], uh[3]);
        *(uint4*)(buf + ALO_OFF + ar * 48 + ak * 2) = make_uint4(ul[0], ul[1], ul[2], ul[3]);
#pragma unroll
        for (int i = 0; i < 4; i++) {
            float h0 = bf16_round(vb[2 * i]), h1 = bf16_round(vb[2 * i + 1]);
            uh[i] = pack_bf16x2(h0, h1);
            ul[i] = pack_bf16x2(vb[2 * i] - h0, vb[2 * i + 1] - h1);
        }
        *(uint4*)(buf + BHI_OFF + br * 272 + bn * 2) = make_uint4(uh[0], uh[1], uh[2], uh[3]);
        *(uint4*)(buf + BLO_OFF + br * 272 + bn * 2) = make_uint4(ul[0], ul[1], ul[2], ul[3]);
    };

    auto do_mma = [&](const char* buf) {
        unsigned base = (unsigned)__cvta_generic_to_shared(buf);
        unsigned bh[8], bl[8];
        LDSM4T(bh,     base + BHI_OFF + b_rel);
        LDSM4T(bh + 4, base + BHI_OFF + b_rel + 32);
        LDSM4T(bl,     base + BLO_OFF + b_rel);
        LDSM4T(bl + 4, base + BLO_OFF + b_rel + 32);
#pragma unroll
        for (int mt = 0; mt < 4; mt++) {
            unsigned ah[4], al[4];
            LDSM4(ah, base + AHI_OFF + a_rel + mt * 768);
            LDSM4(al, base + ALO_OFF + a_rel + mt * 768);
#pragma unroll
            for (int nt = 0; nt < 4; nt++) {
                int bi = ((nt >> 1) << 2) + ((nt & 1) << 1);
                float* c = acc[mt * 4 + nt];
                MMA16816(c, ah, bh[bi], bh[bi + 1]);
                MMA16816(c, ah, bl[bi], bl[bi + 1]);
                MMA16816(c, al, bh[bi], bh[bi + 1]);
            }
        }
    };

    do_sts(gsm[0]);
    __syncthreads();

    int buf = 0;
    for (int kc = 0; kc < K; kc += 16) {
        bool hn = (kc + 16) < K;
        if (hn) {
            ga0 = *(const float4*)(Ap + kc + 16);
            ga1 = *(const float4*)(Ap + kc + 20);
            gb0 = *(const float4*)(Bp + (size_t)(kc + 16) * N);
            gb1 = *(const float4*)(Bp + (size_t)(kc + 16) * N + 4);
        }
        do_mma(gsm[buf]);
        if (hn) {
            do_sts(gsm[buf ^ 1]);
            __syncthreads();
            buf ^= 1;
        }
    }

#pragma unroll
    for (int mt = 0; mt < 4; mt++)
#pragma unroll
        for (int nt = 0; nt < 4; nt++) {
            int r = row0 + wm + mt * 16 + (lane >> 2);
            int c = col0 + wn + nt * 8 + ((lane & 3) << 1);
            float* cr = acc[mt * 4 + nt];
            *(float2*)(C + (size_t)r * N + c)       = make_float2(cr[0], cr[1]);
            *(float2*)(C + (size_t)(r + 8) * N + c) = make_float2(cr[2], cr[3]);
        }
}

// ---------------------------------------------------------------------------
// RoPE in-place on g_qkv
// ---------------------------------------------------------------------------
__global__ void rope_kernel(const int* __restrict__ positions)
{
    int idx = blockIdx.x * blockDim.x + threadIdx.x;
    const int total = MR * 24 * 64;
    if (idx >= total) return;
    int i    = idx & 63;
    int head = (idx >> 6) % 24;
    int row  = idx / (24 * 64);
    int s    = row & (SS - 1);

    int col = (head < NH) ? head * HD : NH * HD + (head - NH) * HD;

    float e    = (float)(2 * i) * (1.0f / 128.0f);
    float invf = 1.0f / powf(10000.0f, e);
    float fr   = (float)positions[s] * invf;
    float c, sn;
    sincosf(fr, &sn, &c);

    float* p = g_qkv + (size_t)row * QKVN + col;
    float x1 = p[i], x2 = p[i + 64];
    p[i]      = x1 * c - x2 * sn;
    p[i + 64] = x2 * c + x1 * sn;
}

// ---------------------------------------------------------------------------
// KV pre-split: convert post-RoPE K and V to hi/lo bf16x2 planes (once).
// idx over [b][kvh][key][d2]; SS*64 = 131072 = 2^17.
// ---------------------------------------------------------------------------
__global__ void kv_prep()
{
    int idx = blockIdx.x * blockDim.x + threadIdx.x;
    if (idx >= KVS_N) return;
    int d2  = idx & 63;
    int key = (idx >> 6) & (SS - 1);
    int bk  = idx >> 17;                 // b*NKV + kvh
    int b = bk >> 3, kvh = bk & 7;
    const float* kp = &g_qkv[(size_t)(b * SS + key) * QKVN + NH * HD + kvh * HD + d2 * 2];
    float k0 = kp[0], k1 = kp[1];
    float v0 = kp[NKV * HD], v1 = kp[NKV * HD + 1];
    float h0 = bf16_round(k0), h1 = bf16_round(k1);
    g_kvs[0][idx] = pack_bf16x2(h0, h1);
    g_kvs[1][idx] = pack_bf16x2(k0 - h0, k1 - h1);
    h0 = bf16_round(v0); h1 = bf16_round(v1);
    g_kvs[2][idx] = pack_bf16x2(h0, h1);
    g_kvs[3][idx] = pack_bf16x2(v0 - h0, v1 - h1);
}

// ---------------------------------------------------------------------------
// Flash attention on tensor cores, pre-split KV + cp.async double buffering.
// BM=128 q rows (8 warps x 16), BN=64 keys/iter. 272B rows (LDSM-clean).
// smem: Qhi 34816 | Qlo 34816 | 2 x { Khi,Klo,Vhi,Vlo 17408 each } = 208896 B
// ---------------------------------------------------------------------------
#define QHI_O  0
#define QLO_O  34816
#define KV_O   69632
#define KVBUF  69632
#define PK_LO  17408
#define PV_HI  34816
#define PV_LO  52224
#define ATTN3_SMEM 208896

__global__ __launch_bounds__(256) void attn_mma()
{
    extern __shared__ char dynsm[];
    unsigned sbase = (unsigned)__cvta_generic_to_shared(dynsm);
    int t = threadIdx.x, lane = t & 31, wid = t >> 5;
    int bh = blockIdx.y, b = bh >> 4, h = bh & 15, kvh = h >> 1;
    int qt = (int)(gridDim.x - 1) - (int)blockIdx.x;   // heavy tiles first
    int row_base = b * SS + qt * 128;
    int seq_base = qt * 128;
    int bkv = (b << 3) + kvh;

    const float scale = 0.08838834764831845f;          // 1/sqrt(128)

    // cp.async staging of one 64-key tile into buffer bb (pure copy)
    int sr = t >> 2, scu = (t & 3) << 4;               // row, uint offset
    auto stage_kv = [&](int kv_base, int bb) {
        size_t gsrc = (size_t)(bkv * SS + kv_base + sr) * 64 + scu;
        unsigned dst0 = sbase + KV_O + bb * KVBUF + sr * 272 + (scu << 2);
#pragma unroll
        for (int p = 0; p < 4; p++) {
            const unsigned* src = &g_kvs[p][gsrc];
            unsigned dst = dst0 + p * PK_LO;
            CPASYNC(dst,      src);
            CPASYNC(dst + 16, src + 4);
            CPASYNC(dst + 32, src + 8);
            CPASYNC(dst + 48, src + 12);
        }
    };

    // stage Q (scaled, hi/lo split), 2 threads per row + kick off KV tile 0
    stage_kv(0, 0);
    CPCOMMIT();
    {
        int r  = t >> 1;
        int c0 = (t & 1) << 6;
        const float* qp = &g_qkv[(size_t)(row_base + r) * QKVN + h * HD];
        char* qh = dynsm + QHI_O + r * 272;
        char* ql = dynsm + QLO_O + r * 272;
#pragma unroll
        for (int i = 0; i < 16; i++) {
            int c = c0 + (i << 2);
            float4 v = *(const float4*)(qp + c);
            v.x *= scale; v.y *= scale; v.z *= scale; v.w *= scale;
            float hx = bf16_round(v.x), hy = bf16_round(v.y);
            float hz = bf16_round(v.z), hw = bf16_round(v.w);
            *(uint2*)(qh + c * 2) = make_uint2(pack_bf16x2(hx, hy), pack_bf16x2(hz, hw));
            *(uint2*)(ql + c * 2) = make_uint2(pack_bf16x2(v.x - hx, v.y - hy),
                                               pack_bf16x2(v.z - hz, v.w - hw));
        }
    }

    float o[16][4];
#pragma unroll
    for (int i = 0; i < 16; i++)
#pragma unroll
        for (int j = 0; j < 4; j++) o[i][j] = 0.f;
    float m2[2] = {-1e30f, -1e30f}, l2[2] = {0.f, 0.f};

    int wr_seq = seq_base + (wid << 4);
    int n_kv = 2 * (qt + 1);

    // per-lane ldsm offsets
    int qa_rel  = ((wid << 4) + (lane & 15)) * 272 + ((lane >> 4) << 4);  // + kc*32
    int kb_key  = ((lane >> 4) << 3) + (lane & 7);                         // + np*16
    int kb_byte = ((lane >> 3) & 1) << 4;                                  // + kc*32
    int v_kl    = (((lane >> 3) & 1) << 3) + (lane & 7);                   // + kc*16
    int v_n     = (lane >> 4) << 3;                                        // + ntp*16

    CPWAIT0();
    __syncthreads();

    int buf = 0;
    for (int j = 0; j < n_kv; j++) {
        bool has_next = (j + 1) < n_kv;
        if (has_next) {                      // prefetch next tile into idle buf
            stage_kv((j + 1) << 6, buf ^ 1);
            CPCOMMIT();
        }
        int kv_base = j << 6;
        unsigned KB = sbase + KV_O + buf * KVBUF;

        // S = Q*K^T (split: hi*hi + hi*lo + lo*hi)
        float s[8][4];
#pragma unroll
        for (int i = 0; i < 8; i++)
#pragma unroll
            for (int jj = 0; jj < 4; jj++) s[i][jj] = 0.f;

#pragma unroll
        for (int kc = 0; kc < 8; kc++) {
            unsigned aqh[4], aql[4];
            LDSM4(aqh, sbase + QHI_O + qa_rel + kc * 32);
            LDSM4(aql, sbase + QLO_O + qa_rel + kc * 32);
#pragma unroll
            for (int np = 0; np < 4; np++) {
                unsigned kbh[4], kbl[4];
                unsigned koff = (unsigned)((kb_key + np * 16) * 272 + kb_byte + kc * 32);
                LDSM4(kbh, KB + koff);
                LDSM4(kbl, KB + PK_LO + koff);
                MMA16816(s[2 * np],     aqh, kbh[0], kbh[1]);
                MMA16816(s[2 * np],     aqh, kbl[0], kbl[1]);
                MMA16816(s[2 * np],     aql, kbh[0], kbh[1]);
                MMA16816(s[2 * np + 1], aqh, kbh[2], kbh[3]);
                MMA16816(s[2 * np + 1], aqh, kbl[2], kbl[3]);
                MMA16816(s[2 * np + 1], aql, kbh[2], kbh[3]);
            }
        }

        // causal mask (only near diagonal)
        if (kv_base + 63 > wr_seq) {
            int r0 = wr_seq + (lane >> 2), r1 = r0 + 8;
#pragma unroll
            for (int nt = 0; nt < 8; nt++) {
                int cgl = kv_base + nt * 8 + ((lane & 3) << 1);
                if (cgl     > r0) s[nt][0] = -1e30f;
                if (cgl + 1 > r0) s[nt][1] = -1e30f;
                if (cgl     > r1) s[nt][2] = -1e30f;
                if (cgl + 1 > r1) s[nt][3] = -1e30f;
            }
        }

        // online softmax (rows r0, r1 per thread; 4-lane row groups)
        float mx0 = -1e30f, mx1 = -1e30f;
#pragma unroll
        for (int nt = 0; nt < 8; nt++) {
            mx0 = fmaxf(mx0, fmaxf(s[nt][0], s[nt][1]));
            mx1 = fmaxf(mx1, fmaxf(s[nt][2], s[nt][3]));
        }
        mx0 = fmaxf(mx0, __shfl_xor_sync(0xffffffffu, mx0, 1));
        mx0 = fmaxf(mx0, __shfl_xor_sync(0xffffffffu, mx0, 2));
        mx1 = fmaxf(mx1, __shfl_xor_sync(0xffffffffu, mx1, 1));
        mx1 = fmaxf(mx1, __shfl_xor_sync(0xffffffffu, mx1, 2));
        float mn0 = fmaxf(m2[0], mx0), mn1 = fmaxf(m2[1], mx1);
        float cr0 = __expf(m2[0] - mn0), cr1 = __expf(m2[1] - mn1);
        m2[0] = mn0; m2[1] = mn1;
        float rs0 = 0.f, rs1 = 0.f;
#pragma unroll
        for (int nt = 0; nt < 8; nt++) {
            s[nt][0] = __expf(s[nt][0] - mn0);
            s[nt][1] = __expf(s[nt][1] - mn0);
            s[nt][2] = __expf(s[nt][2] - mn1);
            s[nt][3] = __expf(s[nt][3] - mn1);
            rs0 += s[nt][0] + s[nt][1];
            rs1 += s[nt][2] + s[nt][3];
        }
        rs0 += __shfl_xor_sync(0xffffffffu, rs0, 1);
        rs0 += __shfl_xor_sync(0xffffffffu, rs0, 2);
        rs1 += __shfl_xor_sync(0xffffffffu, rs1, 1);
        rs1 += __shfl_xor_sync(0xffffffffu, rs1, 2);
        l2[0] = l2[0] * cr0 + rs0;
        l2[1] = l2[1] * cr1 + rs1;
#pragma unroll
        for (int nt = 0; nt < 16; nt++) {
            o[nt][0] *= cr0; o[nt][1] *= cr0;
            o[nt][2] *= cr1; o[nt][3] *= cr1;
        }

        // O += P*V (split: Ph*Vh + Pl*Vh + Ph*Vl); P frags register-converted
#pragma unroll
        for (int kc = 0; kc < 4; kc++) {
            unsigned aph[4], apl[4];
            {
                float p00 = s[2 * kc][0],     p01 = s[2 * kc][1];
                float p10 = s[2 * kc][2],     p11 = s[2 * kc][3];
                float q00 = s[2 * kc + 1][0], q01 = s[2 * kc + 1][1];
                float q10 = s[2 * kc + 1][2], q11 = s[2 * kc + 1][3];
                float h00 = bf16_round(p00), h01 = bf16_round(p01);
                float h10 = bf16_round(p10), h11 = bf16_round(p11);
                float g00 = bf16_round(q00), g01 = bf16_round(q01);
                float g10 = bf16_round(q10), g11 = bf16_round(q11);
                aph[0] = pack_bf16x2(h00, h01); aph[1] = pack_bf16x2(h10, h11);
                aph[2] = pack_bf16x2(g00, g01); aph[3] = pack_bf16x2(g10, g11);
                apl[0] = pack_bf16x2(p00 - h00, p01 - h01);
                apl[1] = pack_bf16x2(p10 - h10, p11 - h11);
                apl[2] = pack_bf16x2(q00 - g00, q01 - g01);
                apl[3] = pack_bf16x2(q10 - g10, q11 - g11);
            }
#pragma unroll
            for (int ntp = 0; ntp < 8; ntp++) {
                unsigned vbh[4], vbl[4];
                unsigned voff = (unsigned)((kc * 16 + v_kl) * 272 + (ntp * 16 + v_n) * 2);
                LDSM4T(vbh, KB + PV_HI + voff);
                LDSM4T(vbl, KB + PV_LO + voff);
                MMA16816(o[2 * ntp],     aph, vbh[0], vbh[1]);
                MMA16816(o[2 * ntp],     apl, vbh[0], vbh[1]);
                MMA16816(o[2 * ntp],     aph, vbl[0], vbl[1]);
                MMA16816(o[2 * ntp + 1], aph, vbh[2], vbh[3]);
                MMA16816(o[2 * ntp + 1], apl, vbh[2], vbh[3]);
                MMA16816(o[2 * ntp + 1], aph, vbl[2], vbl[3]);
            }
        }

        if (has_next) CPWAIT0();             // next tile landed
        __syncthreads();                     // all reads of buf done, writes visible
        buf ^= 1;
    }

    // epilogue: O/l -> g_attn
    float inv0 = 1.f / l2[0], inv1 = 1.f / l2[1];
    int r0 = row_base + (wid << 4) + (lane >> 2);
#pragma unroll
    for (int nt = 0; nt < 16; nt++) {
        int c = h * HD + nt * 8 + ((lane & 3) << 1);
        *(float2*)&g_attn[(size_t)r0 * (NH * HD) + c] =
            make_float2(o[nt][0] * inv0, o[nt][1] * inv0);
        *(float2*)&g_attn[(size_t)(r0 + 8) * (NH * HD) + c] =
            make_float2(o[nt][2] * inv1, o[nt][3] * inv1);
    }
}

// ---------------------------------------------------------------------------
extern "C" void kernel_launch(void* const* d_in, const int* in_sizes, int n_in,
                              void* d_out, int out_size)
{
    const float* hidden    = (const float*)d_in[0];
    const int*   positions = (const int*)d_in[1];
    const float* w_qkv     = (const float*)d_in[2];
    const float* w_o       = (const float*)d_in[3];
    float*       out       = (float*)d_out;
    (void)in_sizes; (void)n_in; (void)out_size;

    void *qkv_p = nullptr, *attn_p = nullptr;
    cudaGetSymbolAddress(&qkv_p, g_qkv);
    cudaGetSymbolAddress(&attn_p, g_attn);

    // 1) QKV projection (tensor-core split-bf16)
    bgemm128<<<dim3(QKVN / 128, MR / 128), 256>>>(hidden, w_qkv, (float*)qkv_p,
                                                  MR, QKVN, HIDN);

    // 2) RoPE
    rope_kernel<<<(MR * 24 * 64 + 255) / 256, 256>>>(positions);

    // 3) KV pre-split (post-RoPE K, V) to bf16 hi/lo planes
    kv_prep<<<KVS_N / 256, 256>>>();

    // 4) causal GQA flash attention (tensor-core, cp.async double-buffered)
    cudaFuncSetAttribute(attn_mma, cudaFuncAttributeMaxDynamicSharedMemorySize,
                         ATTN3_SMEM);
    attn_mma<<<dim3(SS / 128, 32), 256, ATTN3_SMEM>>>();

    // 5) output projection (tensor-core split-bf16)
    bgemm128<<<dim3(HIDN / 128, MR / 128), 256>>>((const float*)attn_p, w_o, out,
                                                  MR, HIDN, NH * HD);
}